// round 5
// baseline (speedup 1.0000x reference)
#include <cuda_runtime.h>
#include <cstdint>

// SeparableConv3D: x[8,3,32,256,256] fp32, depthwise K=5 cross-correlation
// along W, then H, then T, zero 'same' padding each stage.
//
// Fused, 2-rows-per-iteration software pipeline:
//   phase A: cp.async (LDGSTS) 2 x-rows ahead into quad-major slab, zero-fill pads
//   phase B (lane=t, wg=w-quad): W-conv + H-conv 5-deep register ring (shift by 2)
//            -> transposed staging sbufT[w][t]
//   phase C (lane=w, wg=t-quad): T-conv = 3 LDS.128 along t per 4 outputs,
//            from the PREVIOUS iteration's staging buffer
//   ONE __syncthreads per 2 h-rows.

#define NN 8
#define CC 3
#define TT 32
#define HH 256
#define WW 256
#define KK 5

#define WT 32                 // w outputs per block
#define HC 32                 // h rows per block -> grid = 24*8*8 = 1536
#define NIT ((HC + 4) / 2)    // 18 iterations of 2 rows
#define XROW (10 * 32 * 4)    // floats per x row-buffer: [q=0..9][t=0..31][4]
#define XROWB (XROW * 4)      // bytes = 5120
#define STR_T 36              // sbufT per-w stride along t

__device__ __forceinline__ void cp16(uint32_t dst, const float* src, bool pred) {
    int sz = pred ? 16 : 0;
    asm volatile("cp.async.cg.shared.global [%0], [%1], 16, %2;\n"
                 :: "r"(dst), "l"(src), "r"(sz));
}
__device__ __forceinline__ void cp_commit() {
    asm volatile("cp.async.commit_group;\n" ::: "memory");
}
__device__ __forceinline__ void cp_wait0() {
    asm volatile("cp.async.wait_group 0;\n" ::: "memory");
}

__global__ void __launch_bounds__(256, 4)
sepconv3d_fused(const float* __restrict__ x,
                const float* __restrict__ w1,   // along W
                const float* __restrict__ w2,   // along H
                const float* __restrict__ w3,   // along T
                float* __restrict__ out)
{
    __shared__ float xbuf[2][2][XROW];            // [buf][row][q*128 + t*4 + e]
    __shared__ float sbufT[2][2][WT * STR_T];     // [buf][row][w][t]

    const int tid  = threadIdx.x;
    const int lane = tid & 31;     // phase B: = t ; phase C: = w
    const int wg   = tid >> 5;     // phase B: w-quad ; phase C: t-quad

    const int bid = blockIdx.x;               // 0..1535
    const int nc  = bid >> 6;                  // n*3+c
    const int rem = bid & 63;
    const int wt  = rem >> 3;                   // 0..7
    const int hcb = rem & 7;                    // 0..7
    const int c   = nc % CC;

    const int w0 = wt * WT;
    const int h0 = hcb * HC;
    const size_t HW = (size_t)HH * WW;

    const float wW0 = w1[c*KK+0], wW1 = w1[c*KK+1], wW2 = w1[c*KK+2], wW3 = w1[c*KK+3], wW4 = w1[c*KK+4];
    const float wH0 = w2[c*KK+0], wH1 = w2[c*KK+1], wH2 = w2[c*KK+2], wH3 = w2[c*KK+3], wH4 = w2[c*KK+4];
    const float wT0 = w3[c*KK+0], wT1 = w3[c*KK+1], wT2 = w3[c*KK+2], wT3 = w3[c*KK+3], wT4 = w3[c*KK+4];

    const float* xb = x   + (size_t)nc * (TT * HW);
    float*       ob = out + (size_t)nc * (TT * HW);

    // ---- phase A geometry: item A = tid (all), item B = 256+tid (tid<64) ----
    const int trA = tid / 10,  qA = tid - trA * 10;
    const int iB  = 256 + tid;
    const int trB = iB / 10,   qB = iB - trB * 10;
    const int gwA = w0 - 4 + 4 * qA;
    const int gwB = w0 - 4 + 4 * qB;
    const bool wvA = (gwA >= 0) && (gwA < WW);
    const bool hasB = (tid < 64);
    const bool wvB = hasB && (gwB >= 0) && (gwB < WW);
    const float* gA = xb + (size_t)trA * HW + (wvA ? gwA : 0);   // + h*WW
    const float* gB = xb + (size_t)trB * HW + (wvB ? gwB : 0);

    const uint32_t xbase = (uint32_t)__cvta_generic_to_shared(&xbuf[0][0][0]);
    const uint32_t dA0 = xbase + (uint32_t)(qA * 128 + trA * 4) * 4u;
    const uint32_t dB0 = xbase + (uint32_t)(qB * 128 + trB * 4) * 4u;

    // ---- phase C geometry: lane = w, wg = t-quad ----
    const int t0    = 4 * wg;
    const int cbase = lane * STR_T;
    const int oLo   = cbase + max(t0 - 4, 0);    // quad t0-4..t0-1 (clamped)
    const int oMid  = cbase + t0;                // quad t0..t0+3
    const int oHi   = cbase + min(t0 + 4, 28);   // quad t0+4..t0+7 (clamped)
    const float mlo = (wg == 0) ? 0.f : 1.f;     // zero-pad t<0
    const float mhi = (wg == 7) ? 0.f : 1.f;     // zero-pad t>31
    float* obase = ob + (size_t)t0 * HW + w0 + lane;   // + ho*WW, planes j*HW

    // H-conv register ring (W-conv of the last 5 rows)
    float4 g0 = {0,0,0,0}, g1 = {0,0,0,0}, g2 = {0,0,0,0}, g3 = {0,0,0,0}, g4 = {0,0,0,0};

    // ---- prologue: rows it=0,1 (h = h0-2, h0-1) into xbuf[0][0..1] ----
    {
        int h = h0 - 2;
        bool pA = wvA && (h >= 0);
        cp16(dA0 + 0u * XROWB, gA + (size_t)(pA ? h : 0) * WW, pA);
        if (hasB) { bool pB = wvB && (h >= 0); cp16(dB0 + 0u * XROWB, gB + (size_t)(pB ? h : 0) * WW, pB); }
        h = h0 - 1;
        pA = wvA && (h >= 0);
        cp16(dA0 + 1u * XROWB, gA + (size_t)(pA ? h : 0) * WW, pA);
        if (hasB) { bool pB = wvB && (h >= 0); cp16(dB0 + 1u * XROWB, gB + (size_t)(pB ? h : 0) * WW, pB); }
        cp_commit();
        cp_wait0();
    }
    __syncthreads();

    #pragma unroll 2
    for (int ii = 0; ii < NIT; ++ii) {
        const int cur = ii & 1;
        const int nxt = cur ^ 1;

        // ---- 1. phase A: async-load rows it=2ii+2, 2ii+3 (h = h0+2ii, +1) ----
        {
            const bool iv = (ii + 1 < NIT);
            const int ha = h0 + 2 * ii;
            const int hb = ha + 1;
            bool pa = iv && wvA && (ha < HH);
            bool pb = iv && wvA && (hb < HH);
            cp16(dA0 + (uint32_t)(nxt * 2 + 0) * XROWB, gA + (size_t)(pa ? ha : 0) * WW, pa);
            cp16(dA0 + (uint32_t)(nxt * 2 + 1) * XROWB, gA + (size_t)(pb ? hb : 0) * WW, pb);
            if (hasB) {
                bool qa = iv && wvB && (ha < HH);
                bool qb = iv && wvB && (hb < HH);
                cp16(dB0 + (uint32_t)(nxt * 2 + 0) * XROWB, gB + (size_t)(qa ? ha : 0) * WW, qa);
                cp16(dB0 + (uint32_t)(nxt * 2 + 1) * XROWB, gB + (size_t)(qb ? hb : 0) * WW, qb);
            }
            cp_commit();
        }

        // ---- 2. phase B: W-conv both rows, H-conv, store s into sbufT[cur] ----
        float4 r_a, r_b;
        {
            const float* rb0 = &xbuf[cur][0][lane * 4];
            float4 A = *reinterpret_cast<const float4*>(rb0 + (wg + 0) * 128);
            float4 B = *reinterpret_cast<const float4*>(rb0 + (wg + 1) * 128);
            float4 C = *reinterpret_cast<const float4*>(rb0 + (wg + 2) * 128);
            r_a.x = wW0*A.z + wW1*A.w + wW2*B.x + wW3*B.y + wW4*B.z;
            r_a.y = wW0*A.w + wW1*B.x + wW2*B.y + wW3*B.z + wW4*B.w;
            r_a.z = wW0*B.x + wW1*B.y + wW2*B.z + wW3*B.w + wW4*C.x;
            r_a.w = wW0*B.y + wW1*B.z + wW2*B.w + wW3*C.x + wW4*C.y;

            const float* rb1 = &xbuf[cur][1][lane * 4];
            float4 D = *reinterpret_cast<const float4*>(rb1 + (wg + 0) * 128);
            float4 E = *reinterpret_cast<const float4*>(rb1 + (wg + 1) * 128);
            float4 F = *reinterpret_cast<const float4*>(rb1 + (wg + 2) * 128);
            r_b.x = wW0*D.z + wW1*D.w + wW2*E.x + wW3*E.y + wW4*E.z;
            r_b.y = wW0*D.w + wW1*E.x + wW2*E.y + wW3*E.z + wW4*E.w;
            r_b.z = wW0*E.x + wW1*E.y + wW2*E.z + wW3*E.w + wW4*F.x;
            r_b.w = wW0*E.y + wW1*E.z + wW2*E.w + wW3*F.x + wW4*F.y;
        }

        if (ii >= 2) {
            // s_a from (g1,g2,g3,g4,r_a); s_b from (g2,g3,g4,r_a,r_b)
            float* sa = &sbufT[cur][0][4 * wg * STR_T + lane];
            float* sb = &sbufT[cur][1][4 * wg * STR_T + lane];
            sa[0 * STR_T] = wH0*g1.x + wH1*g2.x + wH2*g3.x + wH3*g4.x + wH4*r_a.x;
            sa[1 * STR_T] = wH0*g1.y + wH1*g2.y + wH2*g3.y + wH3*g4.y + wH4*r_a.y;
            sa[2 * STR_T] = wH0*g1.z + wH1*g2.z + wH2*g3.z + wH3*g4.z + wH4*r_a.z;
            sa[3 * STR_T] = wH0*g1.w + wH1*g2.w + wH2*g3.w + wH3*g4.w + wH4*r_a.w;
            sb[0 * STR_T] = wH0*g2.x + wH1*g3.x + wH2*g4.x + wH3*r_a.x + wH4*r_b.x;
            sb[1 * STR_T] = wH0*g2.y + wH1*g3.y + wH2*g4.y + wH3*r_a.y + wH4*r_b.y;
            sb[2 * STR_T] = wH0*g2.z + wH1*g3.z + wH2*g4.z + wH3*r_a.z + wH4*r_b.z;
            sb[3 * STR_T] = wH0*g2.w + wH1*g3.w + wH2*g4.w + wH3*r_a.w + wH4*r_b.w;
        }
        // ring shift by 2 (rename)
        g0 = g2; g1 = g3; g2 = g4; g3 = r_a; g4 = r_b;

        // ---- 3. phase C: T-conv from PREVIOUS sbufT, 2 output rows ----
        if (ii >= 3) {
            const int hoa = h0 + 2 * ii - 6;
            #pragma unroll
            for (int r = 0; r < 2; ++r) {
                const float* sp = sbufT[cur ^ 1][r];
                float4 lo  = *reinterpret_cast<const float4*>(sp + oLo);
                float4 mid = *reinterpret_cast<const float4*>(sp + oMid);
                float4 hi  = *reinterpret_cast<const float4*>(sp + oHi);
                lo.z *= mlo; lo.w *= mlo;
                hi.x *= mhi; hi.y *= mhi;
                float o0 = wT0*lo.z  + wT1*lo.w  + wT2*mid.x + wT3*mid.y + wT4*mid.z;
                float o1 = wT0*lo.w  + wT1*mid.x + wT2*mid.y + wT3*mid.z + wT4*mid.w;
                float o2 = wT0*mid.x + wT1*mid.y + wT2*mid.z + wT3*mid.w + wT4*hi.x;
                float o3 = wT0*mid.y + wT1*mid.z + wT2*mid.w + wT3*hi.x  + wT4*hi.y;
                float* op = obase + (size_t)(hoa + r) * WW;
                op[0]      = o0;
                op[HW]     = o1;
                op[2 * HW] = o2;
                op[3 * HW] = o3;
            }
        }

        cp_wait0();
        __syncthreads();
        // barrier orders: cp.async data in xbuf[nxt] vs next-iter LDS;
        // sbufT[cur] writes vs next-iter phase-C reads;
        // phase-C reads of sbufT[cur^1] vs its rewrite at iter ii+1.
    }

    // ---- epilogue: last 2 output rows from sbufT[(NIT-1)&1] ----
    {
        const int hoa = h0 + 2 * NIT - 6;   // h0 + 30
        #pragma unroll
        for (int r = 0; r < 2; ++r) {
            const float* sp = sbufT[(NIT - 1) & 1][r];
            float4 lo  = *reinterpret_cast<const float4*>(sp + oLo);
            float4 mid = *reinterpret_cast<const float4*>(sp + oMid);
            float4 hi  = *reinterpret_cast<const float4*>(sp + oHi);
            lo.z *= mlo; lo.w *= mlo;
            hi.x *= mhi; hi.y *= mhi;
            float o0 = wT0*lo.z  + wT1*lo.w  + wT2*mid.x + wT3*mid.y + wT4*mid.z;
            float o1 = wT0*lo.w  + wT1*mid.x + wT2*mid.y + wT3*mid.z + wT4*mid.w;
            float o2 = wT0*mid.x + wT1*mid.y + wT2*mid.z + wT3*mid.w + wT4*hi.x;
            float o3 = wT0*mid.y + wT1*mid.z + wT2*mid.w + wT3*hi.x  + wT4*hi.y;
            float* op = obase + (size_t)(hoa + r) * WW;
            op[0]      = o0;
            op[HW]     = o1;
            op[2 * HW] = o2;
            op[3 * HW] = o3;
        }
    }
}

extern "C" void kernel_launch(void* const* d_in, const int* in_sizes, int n_in,
                              void* d_out, int out_size)
{
    const float* x  = (const float*)d_in[0];
    const float* w1 = (const float*)d_in[1];
    const float* w2 = (const float*)d_in[2];
    const float* w3 = (const float*)d_in[3];
    float* out = (float*)d_out;

    // 24 (n*c) * 8 (w tiles) * 8 (h chunks) = 1536 blocks
    sepconv3d_fused<<<NN * CC * (WW / WT) * (HH / HC), 256>>>(x, w1, w2, w3, out);
}

// round 6
// speedup vs baseline: 1.1988x; 1.1988x over previous
#include <cuda_runtime.h>
#include <cstdint>

// SeparableConv3D: x[8,3,32,256,256] fp32, depthwise K=5 cross-correlation
// along W, then H, then T, zero 'same' padding each stage.
//
// Fused, software-pipelined, shuffle-free, t-major staging (R4 structure):
//   phase A: 1-row-ahead LDG register prefetch, committed via STS at iter end
//   phase B (lane=t, wg=w-quad): W-conv from x slab + H-conv register ring,
//            transposed store s(t,w) -> sbufT[w][t]
//   phase C (lane=w, wg=t-quad): T-conv = 3 LDS.128 along t per 4 outputs,
//            from the PREVIOUS iteration's staging buffer, coalesced STG.32
//   ONE __syncthreads per h-row; main loop unrolled 4x to kill ring MOVs
//   and per-iteration address IMADs.

#define NN 8
#define CC 3
#define TT 32
#define HH 256
#define WW 256
#define KK 5

#define WT 32           // w outputs per block
#define HC 32           // h rows per block -> grid = 24*8*8 = 1536
#define XSTRIDE 44      // x slab row stride (conflict-free)
#define STR_T 36        // sbufT per-w stride along t

__global__ void __launch_bounds__(256, 4)
sepconv3d_fused(const float* __restrict__ x,
                const float* __restrict__ w1,   // along W
                const float* __restrict__ w2,   // along H
                const float* __restrict__ w3,   // along T
                float* __restrict__ out)
{
    __shared__ float xbuf[2][TT * XSTRIDE];
    __shared__ float sbufT[2][WT * STR_T];   // [w][t], s = after W+H conv

    const int tid  = threadIdx.x;
    const int lane = tid & 31;     // phase B: = t ; phase C: = w
    const int wg   = tid >> 5;     // phase B: w-quad ; phase C: t-quad

    const int bid = blockIdx.x;               // 0..1535
    const int nc  = bid >> 6;                  // n*3+c
    const int rem = bid & 63;
    const int wt  = rem >> 3;                   // 0..7
    const int hcb = rem & 7;                    // 0..7
    const int c   = nc % CC;

    const int w0 = wt * WT;
    const int h0 = hcb * HC;
    const size_t HW = (size_t)HH * WW;

    const float wW0 = w1[c*KK+0], wW1 = w1[c*KK+1], wW2 = w1[c*KK+2], wW3 = w1[c*KK+3], wW4 = w1[c*KK+4];
    const float wH0 = w2[c*KK+0], wH1 = w2[c*KK+1], wH2 = w2[c*KK+2], wH3 = w2[c*KK+3], wH4 = w2[c*KK+4];
    const float wT0 = w3[c*KK+0], wT1 = w3[c*KK+1], wT2 = w3[c*KK+2], wT3 = w3[c*KK+3], wT4 = w3[c*KK+4];

    const float* xb = x   + (size_t)nc * (TT * HW);
    float*       ob = out + (size_t)nc * (TT * HW);

    // ---- slab-load geometry: items tid and 256+tid (tid<64) ----
    const int trA = tid / 10,  qA = tid - trA * 10;
    const int iB  = 256 + tid;
    const int trB = iB / 10,   qB = iB - trB * 10;
    const int gwA = w0 - 4 + 4 * qA;
    const int gwB = w0 - 4 + 4 * qB;
    const bool wvA = (gwA >= 0) && (gwA < WW);
    const bool hasB = (tid < 64);
    const bool wvB = hasB && (gwB >= 0) && (gwB < WW);
    // incremental prefetch pointers (start at h_in = h0 - 1, it=0's prefetch)
    const float* ptrA = xb + (size_t)trA * HW + (wvA ? gwA : 0) + (size_t)(h0 - 1) * WW;
    const float* ptrB = xb + (size_t)trB * HW + (wvB ? gwB : 0) + (size_t)(h0 - 1) * WW;

    // smem addresses (precomputed)
    float* const xsA0 = &xbuf[0][trA * XSTRIDE + 4 * qA];
    float* const xsA1 = &xbuf[1][trA * XSTRIDE + 4 * qA];
    float* const xsB0 = &xbuf[0][trB * XSTRIDE + 4 * qB];
    float* const xsB1 = &xbuf[1][trB * XSTRIDE + 4 * qB];

    // ---- phase C geometry: lane = w, wg = t-quad ----
    const int t0    = 4 * wg;
    const int cbase = lane * STR_T;
    const int oLo   = cbase + max(t0 - 4, 0);    // quad t0-4..t0-1 (clamped)
    const int oMid  = cbase + t0;                // quad t0..t0+3
    const int oHi   = cbase + min(t0 + 4, 28);   // quad t0+4..t0+7 (clamped)
    const float mlo = (wg == 0) ? 0.f : 1.f;     // zero-pad t<0
    const float mhi = (wg == 7) ? 0.f : 1.f;     // zero-pad t>31
    // incremental output pointer: row ho = h0 + it - 5 used only when it>=5
    float* op = ob + (size_t)t0 * HW + w0 + lane + (size_t)h0 * WW - 5 * WW;

    // H-conv register ring
    float4 g0 = {0,0,0,0}, g1 = {0,0,0,0}, g2 = {0,0,0,0}, g3 = {0,0,0,0}, g4 = {0,0,0,0};
    const int scolbase = 4 * wg;
    float* const sbB0 = &sbufT[0][scolbase * STR_T + lane];   // phase-B store base
    float* const sbB1 = &sbufT[1][scolbase * STR_T + lane];

    // ---- prologue: load row it=0 (h_in = h0-2) into xbuf[0] ----
    {
        const int h_in = h0 - 2;
        const bool hv = (h_in >= 0);
        float4 v = {0,0,0,0};
        if (hv && wvA) v = *reinterpret_cast<const float4*>(ptrA - WW);
        *reinterpret_cast<float4*>(xsA0) = v;
        if (hasB) {
            float4 u = {0,0,0,0};
            if (hv && wvB) u = *reinterpret_cast<const float4*>(ptrB - WW);
            *reinterpret_cast<float4*>(xsB0) = u;
        }
    }
    __syncthreads();

    #pragma unroll 4
    for (int it = 0; it < HC + 4; ++it) {
        const int cur = it & 1;

        // ---- 1. prefetch next x row (h_in = h0 - 1 + it) ----
        float4 p0 = {0,0,0,0}, p1 = {0,0,0,0};
        {
            const int h_in = h0 - 1 + it;
            const bool hv = (it + 1 < HC + 4) && (h_in >= 0) && (h_in < HH);
            if (hv && wvA) p0 = *reinterpret_cast<const float4*>(ptrA);
            if (hv && wvB) p1 = *reinterpret_cast<const float4*>(ptrB);
            ptrA += WW; ptrB += WW;
        }

        // ---- 2. phase B: W-conv + H-ring, transposed store into sbufT[cur] ----
        {
            const float* row = &xbuf[cur][lane * XSTRIDE + scolbase];
            float4 xa = *reinterpret_cast<const float4*>(row);
            float4 xc = *reinterpret_cast<const float4*>(row + 4);
            float4 xe = *reinterpret_cast<const float4*>(row + 8);

            float e0 = xa.z, e1 = xa.w, e2 = xc.x, e3 = xc.y,
                  e4 = xc.z, e5 = xc.w, e6 = xe.x, e7 = xe.y;

            float4 r;
            r.x = wW0*e0 + wW1*e1 + wW2*e2 + wW3*e3 + wW4*e4;
            r.y = wW0*e1 + wW1*e2 + wW2*e3 + wW3*e4 + wW4*e5;
            r.z = wW0*e2 + wW1*e3 + wW2*e4 + wW3*e5 + wW4*e6;
            r.w = wW0*e3 + wW1*e4 + wW2*e5 + wW3*e6 + wW4*e7;

            g0 = g1; g1 = g2; g2 = g3; g3 = g4; g4 = r;

            if (it >= 4) {
                float sx = wH0*g0.x + wH1*g1.x + wH2*g2.x + wH3*g3.x + wH4*g4.x;
                float sy = wH0*g0.y + wH1*g1.y + wH2*g2.y + wH3*g3.y + wH4*g4.y;
                float sz = wH0*g0.z + wH1*g1.z + wH2*g2.z + wH3*g3.z + wH4*g4.z;
                float sw = wH0*g0.w + wH1*g1.w + wH2*g2.w + wH3*g3.w + wH4*g4.w;
                float* sc = cur ? sbB1 : sbB0;
                sc[0 * STR_T] = sx;
                sc[1 * STR_T] = sy;
                sc[2 * STR_T] = sz;
                sc[3 * STR_T] = sw;
            }
        }

        // ---- 3. phase C: T-conv from PREVIOUS sbufT, store row ho = h0+it-5 ----
        if (it >= 5) {
            const float* sb = sbufT[cur ^ 1];
            float4 lo  = *reinterpret_cast<const float4*>(sb + oLo);
            float4 mid = *reinterpret_cast<const float4*>(sb + oMid);
            float4 hi  = *reinterpret_cast<const float4*>(sb + oHi);
            lo.z *= mlo; lo.w *= mlo;     // zero-pad t<0
            hi.x *= mhi; hi.y *= mhi;     // zero-pad t>31

            float o0 = wT0*lo.z  + wT1*lo.w  + wT2*mid.x + wT3*mid.y + wT4*mid.z;
            float o1 = wT0*lo.w  + wT1*mid.x + wT2*mid.y + wT3*mid.z + wT4*mid.w;
            float o2 = wT0*mid.x + wT1*mid.y + wT2*mid.z + wT3*mid.w + wT4*hi.x;
            float o3 = wT0*mid.y + wT1*mid.z + wT2*mid.w + wT3*hi.x  + wT4*hi.y;

            op[0]      = o0;
            op[HW]     = o1;
            op[2 * HW] = o2;
            op[3 * HW] = o3;
        }
        op += WW;

        // ---- 4. commit prefetched x row into xbuf[cur^1] ----
        *reinterpret_cast<float4*>(cur ? xsA0 : xsA1) = p0;
        if (hasB)
            *reinterpret_cast<float4*>(cur ? xsB0 : xsB1) = p1;

        __syncthreads();
        // barrier orders: xbuf[cur^1] STS vs next-iter LDS; sbufT[cur] writes vs
        // next-iter phase-C reads; phase-C reads of sbufT[cur^1] vs iter+1 writes.
    }

    // ---- epilogue: last output row from sbufT[(HC+3)&1], ho = h0+HC-1 ----
    {
        const float* sb = sbufT[(HC + 3) & 1];
        float4 lo  = *reinterpret_cast<const float4*>(sb + oLo);
        float4 mid = *reinterpret_cast<const float4*>(sb + oMid);
        float4 hi  = *reinterpret_cast<const float4*>(sb + oHi);
        lo.z *= mlo; lo.w *= mlo;
        hi.x *= mhi; hi.y *= mhi;

        float o0 = wT0*lo.z  + wT1*lo.w  + wT2*mid.x + wT3*mid.y + wT4*mid.z;
        float o1 = wT0*lo.w  + wT1*mid.x + wT2*mid.y + wT3*mid.z + wT4*mid.w;
        float o2 = wT0*mid.x + wT1*mid.y + wT2*mid.z + wT3*mid.w + wT4*hi.x;
        float o3 = wT0*mid.y + wT1*mid.z + wT2*mid.w + wT3*hi.x  + wT4*hi.y;

        // op has been advanced HC+4 times: points at row h0 + HC - 1
        op[0]      = o0;
        op[HW]     = o1;
        op[2 * HW] = o2;
        op[3 * HW] = o3;
    }
}

extern "C" void kernel_launch(void* const* d_in, const int* in_sizes, int n_in,
                              void* d_out, int out_size)
{
    const float* x  = (const float*)d_in[0];
    const float* w1 = (const float*)d_in[1];
    const float* w2 = (const float*)d_in[2];
    const float* w3 = (const float*)d_in[3];
    float* out = (float*)d_out;

    // 24 (n*c) * 8 (w tiles) * 8 (h chunks) = 1536 blocks
    sepconv3d_fused<<<NN * CC * (WW / WT) * (HH / HC), 256>>>(x, w1, w2, w3, out);
}

// round 7
// speedup vs baseline: 1.2046x; 1.0049x over previous
#include <cuda_runtime.h>
#include <cstdint>

// SeparableConv3D: x[8,3,32,256,256] fp32, depthwise K=5 cross-correlation
// along W, then H, then T, zero 'same' padding each stage.
//
// Fused, software-pipelined, shuffle-free, t-major staging:
//   phase A: 1-row-ahead LDG register prefetch (item A: all threads,
//            item B: warps 4-7), committed via STS at iter end
//   phase B (lane=t, wg=w-quad): W-conv from x slab + H-conv register ring,
//            transposed store s(t,w) -> sbufT[w][t]
//   phase C (warps 0-3 only; lane=w, tg=t-octet): T-conv = 4 LDS.128 along t
//            per 8 outputs, from the PREVIOUS iteration's staging buffer
//   ONE __syncthreads per h-row; main loop unrolled 4x.

#define NN 8
#define CC 3
#define TT 32
#define HH 256
#define WW 256
#define KK 5

#define WT 32           // w outputs per block
#define HC 32           // h rows per block -> grid = 24*8*8 = 1536
#define XSTRIDE 44      // x slab row stride (conflict-free)
#define STR_T 36        // sbufT per-w stride along t

__global__ void __launch_bounds__(256, 4)
sepconv3d_fused(const float* __restrict__ x,
                const float* __restrict__ w1,   // along W
                const float* __restrict__ w2,   // along H
                const float* __restrict__ w3,   // along T
                float* __restrict__ out)
{
    __shared__ float xbuf[2][TT * XSTRIDE];
    __shared__ float sbufT[2][WT * STR_T];   // [w][t], s = after W+H conv

    const int tid  = threadIdx.x;
    const int lane = tid & 31;     // phase B: = t ; phase C: = w
    const int wg   = tid >> 5;     // phase B: w-quad

    const int bid = blockIdx.x;               // 0..1535
    const int nc  = bid >> 6;                  // n*3+c
    const int rem = bid & 63;
    const int wt  = rem >> 3;                   // 0..7
    const int hcb = rem & 7;                    // 0..7
    const int c   = nc % CC;

    const int w0 = wt * WT;
    const int h0 = hcb * HC;
    const size_t HW = (size_t)HH * WW;

    const float wW0 = w1[c*KK+0], wW1 = w1[c*KK+1], wW2 = w1[c*KK+2], wW3 = w1[c*KK+3], wW4 = w1[c*KK+4];
    const float wH0 = w2[c*KK+0], wH1 = w2[c*KK+1], wH2 = w2[c*KK+2], wH3 = w2[c*KK+3], wH4 = w2[c*KK+4];
    const float wT0 = w3[c*KK+0], wT1 = w3[c*KK+1], wT2 = w3[c*KK+2], wT3 = w3[c*KK+3], wT4 = w3[c*KK+4];

    const float* xb = x   + (size_t)nc * (TT * HW);
    float*       ob = out + (size_t)nc * (TT * HW);

    // ---- slab-load geometry: item A = tid (all), item B = warps 4-7 ----
    const int trA = tid / 10,  qA = tid - trA * 10;
    const bool hasB = (tid >= 128) && (tid < 192);
    const int iB  = 256 + (tid - 128);          // 256..319 for warps 4-5... (tid 128..191)
    const int trB = iB / 10,   qB = iB - trB * 10;
    const int gwA = w0 - 4 + 4 * qA;
    const int gwB = w0 - 4 + 4 * qB;
    const bool wvA = (gwA >= 0) && (gwA < WW);
    const bool wvB = hasB && (gwB >= 0) && (gwB < WW);
    // incremental prefetch pointers (start at h_in = h0 - 1, it=0's prefetch)
    const float* ptrA = xb + (size_t)trA * HW + (wvA ? gwA : 0) + (size_t)(h0 - 1) * WW;
    const float* ptrB = xb + (size_t)trB * HW + (wvB ? gwB : 0) + (size_t)(h0 - 1) * WW;

    // smem addresses (precomputed)
    float* const xsA0 = &xbuf[0][trA * XSTRIDE + 4 * qA];
    float* const xsA1 = &xbuf[1][trA * XSTRIDE + 4 * qA];
    float* const xsB0 = &xbuf[0][trB * XSTRIDE + 4 * qB];
    float* const xsB1 = &xbuf[1][trB * XSTRIDE + 4 * qB];

    // ---- phase C geometry: warps 0-3; lane = w, tg = t-octet ----
    const bool doC  = (tid < 128);
    const int tg    = tid >> 5;                  // 0..3 (valid when doC)
    const int t0    = 8 * tg;
    const int cbase = lane * STR_T;
    const int q0off = cbase + max(t0 - 4, 0);    // quad t0-4..t0-1 (clamped)
    const int q1off = cbase + t0;                // quad t0..t0+3
    const int q2off = cbase + t0 + 4;            // quad t0+4..t0+7
    const int q3off = cbase + min(t0 + 8, 28);   // quad t0+8..t0+11 (clamped)
    const float mlo = (tg == 0) ? 0.f : 1.f;     // zero-pad t<0
    const float mhi = (tg == 3) ? 0.f : 1.f;     // zero-pad t>31
    // incremental output pointer: row ho = h0 + it - 5 used only when it>=5
    float* op = ob + (size_t)t0 * HW + w0 + lane + (size_t)h0 * WW - 5 * WW;

    // H-conv register ring
    float4 g0 = {0,0,0,0}, g1 = {0,0,0,0}, g2 = {0,0,0,0}, g3 = {0,0,0,0}, g4 = {0,0,0,0};
    const int scolbase = 4 * wg;
    float* const sbB0 = &sbufT[0][scolbase * STR_T + lane];   // phase-B store base
    float* const sbB1 = &sbufT[1][scolbase * STR_T + lane];

    // ---- prologue: load row it=0 (h_in = h0-2) into xbuf[0] ----
    {
        const int h_in = h0 - 2;
        const bool hv = (h_in >= 0);
        float4 v = {0,0,0,0};
        if (hv && wvA) v = *reinterpret_cast<const float4*>(ptrA - WW);
        *reinterpret_cast<float4*>(xsA0) = v;
        if (hasB) {
            float4 u = {0,0,0,0};
            if (hv && wvB) u = *reinterpret_cast<const float4*>(ptrB - WW);
            *reinterpret_cast<float4*>(xsB0) = u;
        }
    }
    __syncthreads();

    #pragma unroll 4
    for (int it = 0; it < HC + 4; ++it) {
        const int cur = it & 1;

        // ---- 1. prefetch next x row (h_in = h0 - 1 + it) ----
        float4 p0 = {0,0,0,0}, p1 = {0,0,0,0};
        {
            const int h_in = h0 - 1 + it;
            const bool hv = (it + 1 < HC + 4) && (h_in >= 0) && (h_in < HH);
            if (hv && wvA) p0 = *reinterpret_cast<const float4*>(ptrA);
            if (hv && wvB) p1 = *reinterpret_cast<const float4*>(ptrB);
            ptrA += WW; ptrB += WW;
        }

        // ---- 2. phase B: W-conv + H-ring, transposed store into sbufT[cur] ----
        {
            const float* row = &xbuf[cur][lane * XSTRIDE + scolbase];
            float4 xa = *reinterpret_cast<const float4*>(row);
            float4 xc = *reinterpret_cast<const float4*>(row + 4);
            float4 xe = *reinterpret_cast<const float4*>(row + 8);

            float e0 = xa.z, e1 = xa.w, e2 = xc.x, e3 = xc.y,
                  e4 = xc.z, e5 = xc.w, e6 = xe.x, e7 = xe.y;

            float4 r;
            r.x = wW0*e0 + wW1*e1 + wW2*e2 + wW3*e3 + wW4*e4;
            r.y = wW0*e1 + wW1*e2 + wW2*e3 + wW3*e4 + wW4*e5;
            r.z = wW0*e2 + wW1*e3 + wW2*e4 + wW3*e5 + wW4*e6;
            r.w = wW0*e3 + wW1*e4 + wW2*e5 + wW3*e6 + wW4*e7;

            g0 = g1; g1 = g2; g2 = g3; g3 = g4; g4 = r;

            if (it >= 4) {
                float sx = wH0*g0.x + wH1*g1.x + wH2*g2.x + wH3*g3.x + wH4*g4.x;
                float sy = wH0*g0.y + wH1*g1.y + wH2*g2.y + wH3*g3.y + wH4*g4.y;
                float sz = wH0*g0.z + wH1*g1.z + wH2*g2.z + wH3*g3.z + wH4*g4.z;
                float sw = wH0*g0.w + wH1*g1.w + wH2*g2.w + wH3*g3.w + wH4*g4.w;
                float* sc = cur ? sbB1 : sbB0;
                sc[0 * STR_T] = sx;
                sc[1 * STR_T] = sy;
                sc[2 * STR_T] = sz;
                sc[3 * STR_T] = sw;
            }
        }

        // ---- 3. phase C (warps 0-3): T-conv from PREVIOUS sbufT, 8 t-outputs ----
        if (doC && it >= 5) {
            const float* sb = sbufT[cur ^ 1];
            float4 q0 = *reinterpret_cast<const float4*>(sb + q0off);
            float4 q1 = *reinterpret_cast<const float4*>(sb + q1off);
            float4 q2 = *reinterpret_cast<const float4*>(sb + q2off);
            float4 q3 = *reinterpret_cast<const float4*>(sb + q3off);
            q0.z *= mlo; q0.w *= mlo;     // zero-pad t<0
            q3.x *= mhi; q3.y *= mhi;     // zero-pad t>31

            float o0 = wT0*q0.z + wT1*q0.w + wT2*q1.x + wT3*q1.y + wT4*q1.z;
            float o1 = wT0*q0.w + wT1*q1.x + wT2*q1.y + wT3*q1.z + wT4*q1.w;
            float o2 = wT0*q1.x + wT1*q1.y + wT2*q1.z + wT3*q1.w + wT4*q2.x;
            float o3 = wT0*q1.y + wT1*q1.z + wT2*q1.w + wT3*q2.x + wT4*q2.y;
            float o4 = wT0*q1.z + wT1*q1.w + wT2*q2.x + wT3*q2.y + wT4*q2.z;
            float o5 = wT0*q1.w + wT1*q2.x + wT2*q2.y + wT3*q2.z + wT4*q2.w;
            float o6 = wT0*q2.x + wT1*q2.y + wT2*q2.z + wT3*q2.w + wT4*q3.x;
            float o7 = wT0*q2.y + wT1*q2.z + wT2*q2.w + wT3*q3.x + wT4*q3.y;

            op[0]      = o0;
            op[1 * HW] = o1;
            op[2 * HW] = o2;
            op[3 * HW] = o3;
            op[4 * HW] = o4;
            op[5 * HW] = o5;
            op[6 * HW] = o6;
            op[7 * HW] = o7;
        }
        op += WW;

        // ---- 4. commit prefetched x row into xbuf[cur^1] ----
        *reinterpret_cast<float4*>(cur ? xsA0 : xsA1) = p0;
        if (hasB)
            *reinterpret_cast<float4*>(cur ? xsB0 : xsB1) = p1;

        __syncthreads();
        // barrier orders: xbuf[cur^1] STS vs next-iter LDS; sbufT[cur] writes vs
        // next-iter phase-C reads; phase-C reads of sbufT[cur^1] vs iter+1 writes.
    }

    // ---- epilogue: last output row from sbufT[(HC+3)&1], ho = h0+HC-1 ----
    if (doC) {
        const float* sb = sbufT[(HC + 3) & 1];
        float4 q0 = *reinterpret_cast<const float4*>(sb + q0off);
        float4 q1 = *reinterpret_cast<const float4*>(sb + q1off);
        float4 q2 = *reinterpret_cast<const float4*>(sb + q2off);
        float4 q3 = *reinterpret_cast<const float4*>(sb + q3off);
        q0.z *= mlo; q0.w *= mlo;
        q3.x *= mhi; q3.y *= mhi;

        float o0 = wT0*q0.z + wT1*q0.w + wT2*q1.x + wT3*q1.y + wT4*q1.z;
        float o1 = wT0*q0.w + wT1*q1.x + wT2*q1.y + wT3*q1.z + wT4*q1.w;
        float o2 = wT0*q1.x + wT1*q1.y + wT2*q1.z + wT3*q1.w + wT4*q2.x;
        float o3 = wT0*q1.y + wT1*q1.z + wT2*q1.w + wT3*q2.x + wT4*q2.y;
        float o4 = wT0*q1.z + wT1*q1.w + wT2*q2.x + wT3*q2.y + wT4*q2.z;
        float o5 = wT0*q1.w + wT1*q2.x + wT2*q2.y + wT3*q2.z + wT4*q2.w;
        float o6 = wT0*q2.x + wT1*q2.y + wT2*q2.z + wT3*q2.w + wT4*q3.x;
        float o7 = wT0*q2.y + wT1*q2.z + wT2*q2.w + wT3*q3.x + wT4*q3.y;

        // op has been advanced HC+4 times: points at row h0 + HC - 1
        op[0]      = o0;
        op[1 * HW] = o1;
        op[2 * HW] = o2;
        op[3 * HW] = o3;
        op[4 * HW] = o4;
        op[5 * HW] = o5;
        op[6 * HW] = o6;
        op[7 * HW] = o7;
    }
}

extern "C" void kernel_launch(void* const* d_in, const int* in_sizes, int n_in,
                              void* d_out, int out_size)
{
    const float* x  = (const float*)d_in[0];
    const float* w1 = (const float*)d_in[1];
    const float* w2 = (const float*)d_in[2];
    const float* w3 = (const float*)d_in[3];
    float* out = (float*)d_out;

    // 24 (n*c) * 8 (w tiles) * 8 (h chunks) = 1536 blocks
    sepconv3d_fused<<<NN * CC * (WW / WT) * (HH / HC), 256>>>(x, w1, w2, w3, out);
}